// round 1
// baseline (speedup 1.0000x reference)
#include <cuda_runtime.h>
#include <cstdint>

#define BATCH   4096
#define NB      64
#define KDIM    64
#define IN_DIM  256
#define NTOT    4096
#define DT_C    0.05f
#define TAU_EPS 1e-6f

typedef unsigned long long u64;

// Scratch for net0 = tanh(u_t @ W_in^T + b_in)  [BATCH, K]
__device__ float g_net0[BATCH * KDIM];

// ---------------------------------------------------------------------------
// f32x2 packed helpers (Blackwell FFMA2 path — only reachable via PTX)
// ---------------------------------------------------------------------------
__device__ __forceinline__ u64 ffma2(u64 a, u64 b, u64 c) {
    u64 d;
    asm("fma.rn.f32x2 %0, %1, %2, %3;" : "=l"(d) : "l"(a), "l"(b), "l"(c));
    return d;
}
__device__ __forceinline__ u64 pack2(float lo, float hi) {
    u64 r;
    asm("mov.b64 %0, {%1, %2};" : "=l"(r) : "f"(lo), "f"(hi));
    return r;
}
__device__ __forceinline__ float2 unpack2(u64 v) {
    float2 r;
    asm("mov.b64 {%0, %1}, %2;" : "=f"(r.x), "=f"(r.y) : "l"(v));
    return r;
}

// ---------------------------------------------------------------------------
// Kernel 1: net0[b,o] = tanh( sum_i u[b,i]*Wi[o,i] + bi[o] )   (K = 256)
// grid = 64 batch tiles of 64, block = 256 threads, thread tile 4b x 4o
// ---------------------------------------------------------------------------
__global__ void __launch_bounds__(256) net0_kernel(const float* __restrict__ u,
                                                   const float* __restrict__ Wi,
                                                   const float* __restrict__ bi) {
    __shared__ float su[64][65];
    __shared__ float sw[64][65];
    const int t  = threadIdx.x;
    const int bt = blockIdx.x;
    const int tx = t & 15, ty = t >> 4;
    const int ob = tx * 4, bb = ty * 4;

    float acc[4][4];
#pragma unroll
    for (int p = 0; p < 4; p++)
#pragma unroll
        for (int q = 0; q < 4; q++) acc[p][q] = 0.f;

    for (int kc = 0; kc < IN_DIM; kc += 64) {
        __syncthreads();
#pragma unroll
        for (int r = 0; r < 4; r++) {
            int idx = t + r * 256;          // 1024 float4 chunks total
            int row = idx >> 4;
            int col = (idx & 15) * 4;
            float4 v = *(const float4*)&u[(bt * 64 + row) * IN_DIM + kc + col];
            su[row][col + 0] = v.x; su[row][col + 1] = v.y;
            su[row][col + 2] = v.z; su[row][col + 3] = v.w;
            float4 w = *(const float4*)&Wi[row * IN_DIM + kc + col];
            sw[row][col + 0] = w.x; sw[row][col + 1] = w.y;
            sw[row][col + 2] = w.z; sw[row][col + 3] = w.w;
        }
        __syncthreads();
#pragma unroll 8
        for (int i = 0; i < 64; i++) {
            float wv[4], yv[4];
#pragma unroll
            for (int q = 0; q < 4; q++) wv[q] = sw[ob + q][i];
#pragma unroll
            for (int p = 0; p < 4; p++) yv[p] = su[bb + p][i];
#pragma unroll
            for (int p = 0; p < 4; p++)
#pragma unroll
                for (int q = 0; q < 4; q++) acc[p][q] = fmaf(yv[p], wv[q], acc[p][q]);
        }
    }
#pragma unroll
    for (int p = 0; p < 4; p++)
#pragma unroll
        for (int q = 0; q < 4; q++)
            g_net0[(bt * 64 + bb + p) * KDIM + ob + q] = tanhf(acc[p][q] + bi[ob + q]);
}

// ---------------------------------------------------------------------------
// Kernel 2: main LTC update. grid = (64 batch tiles, 64 blocks j), 256 thr.
// Weights stored in SMEM transposed + duplicated into (w,w) f32x2 pairs so
// each FFMA2 processes 2 batch rows. y/net tiles packed over batch pairs,
// row stride 66 (8-byte elems) for conflict-free LDS.
// ---------------------------------------------------------------------------
struct SmemMain {
    u64   Wd0[64 * 64];   // dup'd transposed weights (W_fwd, then E_l)
    u64   Wd1[64 * 64];   // dup'd transposed weights (W_rec, then E_l_r)
    u64   ypp[32 * 66];   // y prev-block tile, packed batch pairs
    u64   ypc[32 * 66];   // y cur-block tile
    u64   sno[32 * 66];   // net_out (tanh'd)
    u64   snr[32 * 66];   // net_rec (tanh'd)
    float bfs[64];
    float brs[64];
    float itau[64];
};

__device__ __forceinline__ void load_wdup(u64* dst, const float* __restrict__ w, int t) {
    // w: [64 o][64 i] row-major -> dst[i*64 + o] = (w,w)
    for (int idx = t; idx < 1024; idx += 256) {
        int o  = idx >> 4;
        int i4 = (idx & 15) * 4;
        float4 v = *(const float4*)&w[o * 64 + i4];
        dst[(i4 + 0) * 64 + o] = pack2(v.x, v.x);
        dst[(i4 + 1) * 64 + o] = pack2(v.y, v.y);
        dst[(i4 + 2) * 64 + o] = pack2(v.z, v.z);
        dst[(i4 + 3) * 64 + o] = pack2(v.w, v.w);
    }
}

__global__ void __launch_bounds__(256) ltc_main(
    const float* __restrict__ y,
    const float* __restrict__ tau_raw,
    const float* __restrict__ Wf,  const float* __restrict__ bf,
    const float* __restrict__ Wr,  const float* __restrict__ br,
    const float* __restrict__ El,  const float* __restrict__ Elr,
    float* __restrict__ out)
{
    extern __shared__ char smraw[];
    SmemMain& S = *reinterpret_cast<SmemMain*>(smraw);

    const int t    = threadIdx.x;
    const int bt   = blockIdx.x;
    const int j    = blockIdx.y;
    const int row0 = bt * 64;
    const int tx = t & 15, ty = t >> 4;
    const int ob  = tx * 4;
    const int bp0 = ty * 2;      // this thread's two batch pairs -> batches 4ty..4ty+3

    // ---------------- Phase A loads ----------------
    load_wdup(S.Wd1, Wr + j * 4096, t);
    if (j > 0) {
        load_wdup(S.Wd0, Wf + (j - 1) * 4096, t);
        for (int idx = t; idx < 2048; idx += 256) {
            int bp = idx >> 6, i = idx & 63;
            const float* p = &y[(row0 + 2 * bp) * NTOT + (j - 1) * 64 + i];
            S.ypp[bp * 66 + i] = pack2(p[0], p[NTOT]);
        }
        if (t < 64) S.bfs[t] = bf[(j - 1) * 64 + t];
    } else {
        for (int idx = t; idx < 2048; idx += 256) {
            int bp = idx >> 6, o = idx & 63;
            const float* p = &g_net0[(row0 + 2 * bp) * KDIM + o];
            S.sno[bp * 66 + o] = pack2(p[0], p[KDIM]);
        }
    }
    for (int idx = t; idx < 2048; idx += 256) {
        int bp = idx >> 6, i = idx & 63;
        const float* p = &y[(row0 + 2 * bp) * NTOT + j * 64 + i];
        S.ypc[bp * 66 + i] = pack2(p[0], p[NTOT]);
    }
    if (t < 64) {
        S.brs[t] = br[j * 64 + t];
        float x  = tau_raw[j * 64 + t];
        float sp = (x > 20.f) ? x : log1pf(expf(x));
        S.itau[t] = 1.0f / (sp + TAU_EPS);
    }
    __syncthreads();

    // ---------------- Phase A: net_rec = tanh(y_cur @ Wr^T + br) ----------------
    {
        u64 acc[2][4];
#pragma unroll
        for (int q = 0; q < 4; q++) {
            u64 bv = pack2(S.brs[ob + q], S.brs[ob + q]);
            acc[0][q] = bv; acc[1][q] = bv;
        }
#pragma unroll 8
        for (int i = 0; i < 64; i++) {
            ulonglong2 w01 = *(const ulonglong2*)&S.Wd1[i * 64 + ob];
            ulonglong2 w23 = *(const ulonglong2*)&S.Wd1[i * 64 + ob + 2];
            u64 y0 = S.ypc[(bp0 + 0) * 66 + i];
            u64 y1 = S.ypc[(bp0 + 1) * 66 + i];
            acc[0][0] = ffma2(y0, w01.x, acc[0][0]);
            acc[0][1] = ffma2(y0, w01.y, acc[0][1]);
            acc[0][2] = ffma2(y0, w23.x, acc[0][2]);
            acc[0][3] = ffma2(y0, w23.y, acc[0][3]);
            acc[1][0] = ffma2(y1, w01.x, acc[1][0]);
            acc[1][1] = ffma2(y1, w01.y, acc[1][1]);
            acc[1][2] = ffma2(y1, w23.x, acc[1][2]);
            acc[1][3] = ffma2(y1, w23.y, acc[1][3]);
        }
#pragma unroll
        for (int p = 0; p < 2; p++)
#pragma unroll
            for (int q = 0; q < 4; q++) {
                float2 v = unpack2(acc[p][q]);
                S.snr[(bp0 + p) * 66 + ob + q] = pack2(tanhf(v.x), tanhf(v.y));
            }
    }

    // ---------------- Phase A: net_out (j>0: tanh(y_prev @ Wf^T + bf)) ----------------
    if (j > 0) {
        u64 acc[2][4];
#pragma unroll
        for (int q = 0; q < 4; q++) {
            u64 bv = pack2(S.bfs[ob + q], S.bfs[ob + q]);
            acc[0][q] = bv; acc[1][q] = bv;
        }
#pragma unroll 8
        for (int i = 0; i < 64; i++) {
            ulonglong2 w01 = *(const ulonglong2*)&S.Wd0[i * 64 + ob];
            ulonglong2 w23 = *(const ulonglong2*)&S.Wd0[i * 64 + ob + 2];
            u64 y0 = S.ypp[(bp0 + 0) * 66 + i];
            u64 y1 = S.ypp[(bp0 + 1) * 66 + i];
            acc[0][0] = ffma2(y0, w01.x, acc[0][0]);
            acc[0][1] = ffma2(y0, w01.y, acc[0][1]);
            acc[0][2] = ffma2(y0, w23.x, acc[0][2]);
            acc[0][3] = ffma2(y0, w23.y, acc[0][3]);
            acc[1][0] = ffma2(y1, w01.x, acc[1][0]);
            acc[1][1] = ffma2(y1, w01.y, acc[1][1]);
            acc[1][2] = ffma2(y1, w23.x, acc[1][2]);
            acc[1][3] = ffma2(y1, w23.y, acc[1][3]);
        }
#pragma unroll
        for (int p = 0; p < 2; p++)
#pragma unroll
            for (int q = 0; q < 4; q++) {
                float2 v = unpack2(acc[p][q]);
                S.sno[(bp0 + p) * 66 + ob + q] = pack2(tanhf(v.x), tanhf(v.y));
            }
    }
    __syncthreads();

    // ---------------- Phase B loads: E_l -> Wd0, E_l_r -> Wd1 ----------------
    load_wdup(S.Wd0, El  + j * 4096, t);
    load_wdup(S.Wd1, Elr + j * 4096, t);
    __syncthreads();

    // ---------------- Phase B: drive = net_out @ El^T + net_rec @ Elr^T ----------------
    u64 accD[2][4];
#pragma unroll
    for (int p = 0; p < 2; p++)
#pragma unroll
        for (int q = 0; q < 4; q++) accD[p][q] = pack2(0.f, 0.f);

#pragma unroll 4
    for (int i = 0; i < 64; i++) {
        ulonglong2 e01 = *(const ulonglong2*)&S.Wd0[i * 64 + ob];
        ulonglong2 e23 = *(const ulonglong2*)&S.Wd0[i * 64 + ob + 2];
        ulonglong2 r01 = *(const ulonglong2*)&S.Wd1[i * 64 + ob];
        ulonglong2 r23 = *(const ulonglong2*)&S.Wd1[i * 64 + ob + 2];
        u64 n0 = S.sno[(bp0 + 0) * 66 + i];
        u64 n1 = S.sno[(bp0 + 1) * 66 + i];
        u64 m0 = S.snr[(bp0 + 0) * 66 + i];
        u64 m1 = S.snr[(bp0 + 1) * 66 + i];
        accD[0][0] = ffma2(n0, e01.x, accD[0][0]);
        accD[0][1] = ffma2(n0, e01.y, accD[0][1]);
        accD[0][2] = ffma2(n0, e23.x, accD[0][2]);
        accD[0][3] = ffma2(n0, e23.y, accD[0][3]);
        accD[1][0] = ffma2(n1, e01.x, accD[1][0]);
        accD[1][1] = ffma2(n1, e01.y, accD[1][1]);
        accD[1][2] = ffma2(n1, e23.x, accD[1][2]);
        accD[1][3] = ffma2(n1, e23.y, accD[1][3]);
        accD[0][0] = ffma2(m0, r01.x, accD[0][0]);
        accD[0][1] = ffma2(m0, r01.y, accD[0][1]);
        accD[0][2] = ffma2(m0, r23.x, accD[0][2]);
        accD[0][3] = ffma2(m0, r23.y, accD[0][3]);
        accD[1][0] = ffma2(m1, r01.x, accD[1][0]);
        accD[1][1] = ffma2(m1, r01.y, accD[1][1]);
        accD[1][2] = ffma2(m1, r23.x, accD[1][2]);
        accD[1][3] = ffma2(m1, r23.y, accD[1][3]);
    }

    // ---------------- Epilogue ----------------
    float vals[4][4];   // [local batch 0..3][o sub 0..3]
#pragma unroll
    for (int p = 0; p < 2; p++)
#pragma unroll
        for (int q = 0; q < 4; q++) {
            float2 dr  = unpack2(accD[p][q]);
            float2 nov = unpack2(S.sno[(bp0 + p) * 66 + ob + q]);
            float2 nrv = unpack2(S.snr[(bp0 + p) * 66 + ob + q]);
            float2 yv  = unpack2(S.ypc[(bp0 + p) * 66 + ob + q]);
            float  it  = S.itau[ob + q];
            vals[2 * p + 0][q] = (yv.x + DT_C * dr.x) /
                                 (1.f + DT_C * (it + fabsf(nov.x) + fabsf(nrv.x)));
            vals[2 * p + 1][q] = (yv.y + DT_C * dr.y) /
                                 (1.f + DT_C * (it + fabsf(nov.y) + fabsf(nrv.y)));
        }
#pragma unroll
    for (int bl = 0; bl < 4; bl++) {
        int row = row0 + ty * 4 + bl;
        float4 v = make_float4(vals[bl][0], vals[bl][1], vals[bl][2], vals[bl][3]);
        *(float4*)&out[row * NTOT + j * 64 + ob] = v;
    }
}

// ---------------------------------------------------------------------------
extern "C" void kernel_launch(void* const* d_in, const int* in_sizes, int n_in,
                              void* d_out, int out_size) {
    const float* y   = (const float*)d_in[0];
    const float* u_t = (const float*)d_in[1];
    const float* tau = (const float*)d_in[2];
    const float* Wi  = (const float*)d_in[3];
    const float* bi  = (const float*)d_in[4];
    const float* Wf  = (const float*)d_in[5];
    const float* bf  = (const float*)d_in[6];
    const float* Wr  = (const float*)d_in[7];
    const float* br  = (const float*)d_in[8];
    const float* El  = (const float*)d_in[9];
    const float* Elr = (const float*)d_in[10];
    float* out = (float*)d_out;

    cudaFuncSetAttribute(ltc_main, cudaFuncAttributeMaxDynamicSharedMemorySize,
                         (int)sizeof(SmemMain));

    net0_kernel<<<BATCH / 64, 256>>>(u_t, Wi, bi);
    ltc_main<<<dim3(BATCH / 64, NB), 256, sizeof(SmemMain)>>>(
        y, tau, Wf, bf, Wr, br, El, Elr, out);
}

// round 2
// speedup vs baseline: 1.0001x; 1.0001x over previous
#include <cuda_runtime.h>
#include <cstdint>

#define BATCH   4096
#define NB      64
#define KDIM    64
#define IN_DIM  256
#define NTOT    4096
#define DT_C    0.05f
#define TAU_EPS 1e-6f

typedef unsigned long long u64;

// Scratch for net0 = tanh(u_t @ W_in^T + b_in)  [BATCH, K]
__device__ float g_net0[BATCH * KDIM];

// ---------------------------------------------------------------------------
// f32x2 packed helpers (Blackwell FFMA2 path — only reachable via PTX)
// ---------------------------------------------------------------------------
__device__ __forceinline__ u64 ffma2(u64 a, u64 b, u64 c) {
    u64 d;
    asm("fma.rn.f32x2 %0, %1, %2, %3;" : "=l"(d) : "l"(a), "l"(b), "l"(c));
    return d;
}
__device__ __forceinline__ u64 pack2(float lo, float hi) {
    u64 r;
    asm("mov.b64 %0, {%1, %2};" : "=l"(r) : "f"(lo), "f"(hi));
    return r;
}
__device__ __forceinline__ float2 unpack2(u64 v) {
    float2 r;
    asm("mov.b64 {%0, %1}, %2;" : "=f"(r.x), "=f"(r.y) : "l"(v));
    return r;
}

// ---------------------------------------------------------------------------
// Kernel 1: net0[b,o] = tanh( sum_i u[b,i]*Wi[o,i] + bi[o] )   (K = 256)
// grid = 64 batch tiles of 64, block = 256 threads, thread tile 4b x 4o
// ---------------------------------------------------------------------------
__global__ void __launch_bounds__(256) net0_kernel(const float* __restrict__ u,
                                                   const float* __restrict__ Wi,
                                                   const float* __restrict__ bi) {
    __shared__ float su[64][65];
    __shared__ float sw[64][65];
    const int t  = threadIdx.x;
    const int bt = blockIdx.x;
    const int tx = t & 15, ty = t >> 4;
    const int ob = tx * 4, bb = ty * 4;

    float acc[4][4];
#pragma unroll
    for (int p = 0; p < 4; p++)
#pragma unroll
        for (int q = 0; q < 4; q++) acc[p][q] = 0.f;

    for (int kc = 0; kc < IN_DIM; kc += 64) {
        __syncthreads();
#pragma unroll
        for (int r = 0; r < 4; r++) {
            int idx = t + r * 256;          // 1024 float4 chunks total
            int row = idx >> 4;
            int col = (idx & 15) * 4;
            float4 v = *(const float4*)&u[(bt * 64 + row) * IN_DIM + kc + col];
            su[row][col + 0] = v.x; su[row][col + 1] = v.y;
            su[row][col + 2] = v.z; su[row][col + 3] = v.w;
            float4 w = *(const float4*)&Wi[row * IN_DIM + kc + col];
            sw[row][col + 0] = w.x; sw[row][col + 1] = w.y;
            sw[row][col + 2] = w.z; sw[row][col + 3] = w.w;
        }
        __syncthreads();
#pragma unroll 8
        for (int i = 0; i < 64; i++) {
            float wv[4], yv[4];
#pragma unroll
            for (int q = 0; q < 4; q++) wv[q] = sw[ob + q][i];
#pragma unroll
            for (int p = 0; p < 4; p++) yv[p] = su[bb + p][i];
#pragma unroll
            for (int p = 0; p < 4; p++)
#pragma unroll
                for (int q = 0; q < 4; q++) acc[p][q] = fmaf(yv[p], wv[q], acc[p][q]);
        }
    }
#pragma unroll
    for (int p = 0; p < 4; p++)
#pragma unroll
        for (int q = 0; q < 4; q++)
            g_net0[(bt * 64 + bb + p) * KDIM + ob + q] = tanhf(acc[p][q] + bi[ob + q]);
}

// ---------------------------------------------------------------------------
// Kernel 2: main LTC update. grid = (64 batch tiles, 64 blocks j), 256 thr.
// Weights stored in SMEM transposed + duplicated into (w,w) f32x2 pairs so
// each FFMA2 processes 2 batch rows. y/net tiles packed over batch pairs,
// row stride 66 (8-byte elems) for conflict-free LDS.
// ---------------------------------------------------------------------------
struct SmemMain {
    u64   Wd0[64 * 64];   // dup'd transposed weights (W_fwd, then E_l)
    u64   Wd1[64 * 64];   // dup'd transposed weights (W_rec, then E_l_r)
    u64   ypp[32 * 66];   // y prev-block tile, packed batch pairs
    u64   ypc[32 * 66];   // y cur-block tile
    u64   sno[32 * 66];   // net_out (tanh'd)
    u64   snr[32 * 66];   // net_rec (tanh'd)
    float bfs[64];
    float brs[64];
    float itau[64];
};

__device__ __forceinline__ void load_wdup(u64* dst, const float* __restrict__ w, int t) {
    // w: [64 o][64 i] row-major -> dst[i*64 + o] = (w,w)
    for (int idx = t; idx < 1024; idx += 256) {
        int o  = idx >> 4;
        int i4 = (idx & 15) * 4;
        float4 v = *(const float4*)&w[o * 64 + i4];
        dst[(i4 + 0) * 64 + o] = pack2(v.x, v.x);
        dst[(i4 + 1) * 64 + o] = pack2(v.y, v.y);
        dst[(i4 + 2) * 64 + o] = pack2(v.z, v.z);
        dst[(i4 + 3) * 64 + o] = pack2(v.w, v.w);
    }
}

__global__ void __launch_bounds__(256) ltc_main(
    const float* __restrict__ y,
    const float* __restrict__ tau_raw,
    const float* __restrict__ Wf,  const float* __restrict__ bf,
    const float* __restrict__ Wr,  const float* __restrict__ br,
    const float* __restrict__ El,  const float* __restrict__ Elr,
    float* __restrict__ out)
{
    extern __shared__ char smraw[];
    SmemMain& S = *reinterpret_cast<SmemMain*>(smraw);

    const int t    = threadIdx.x;
    const int bt   = blockIdx.x;
    const int j    = blockIdx.y;
    const int row0 = bt * 64;
    const int tx = t & 15, ty = t >> 4;
    const int ob  = tx * 4;
    const int bp0 = ty * 2;      // this thread's two batch pairs -> batches 4ty..4ty+3

    // ---------------- Phase A loads ----------------
    load_wdup(S.Wd1, Wr + j * 4096, t);
    if (j > 0) {
        load_wdup(S.Wd0, Wf + (j - 1) * 4096, t);
        for (int idx = t; idx < 2048; idx += 256) {
            int bp = idx >> 6, i = idx & 63;
            const float* p = &y[(row0 + 2 * bp) * NTOT + (j - 1) * 64 + i];
            S.ypp[bp * 66 + i] = pack2(p[0], p[NTOT]);
        }
        if (t < 64) S.bfs[t] = bf[(j - 1) * 64 + t];
    } else {
        for (int idx = t; idx < 2048; idx += 256) {
            int bp = idx >> 6, o = idx & 63;
            const float* p = &g_net0[(row0 + 2 * bp) * KDIM + o];
            S.sno[bp * 66 + o] = pack2(p[0], p[KDIM]);
        }
    }
    for (int idx = t; idx < 2048; idx += 256) {
        int bp = idx >> 6, i = idx & 63;
        const float* p = &y[(row0 + 2 * bp) * NTOT + j * 64 + i];
        S.ypc[bp * 66 + i] = pack2(p[0], p[NTOT]);
    }
    if (t < 64) {
        S.brs[t] = br[j * 64 + t];
        float x  = tau_raw[j * 64 + t];
        float sp = (x > 20.f) ? x : log1pf(expf(x));
        S.itau[t] = 1.0f / (sp + TAU_EPS);
    }
    __syncthreads();

    // ---------------- Phase A: net_rec = tanh(y_cur @ Wr^T + br) ----------------
    {
        u64 acc[2][4];
#pragma unroll
        for (int q = 0; q < 4; q++) {
            u64 bv = pack2(S.brs[ob + q], S.brs[ob + q]);
            acc[0][q] = bv; acc[1][q] = bv;
        }
#pragma unroll 8
        for (int i = 0; i < 64; i++) {
            ulonglong2 w01 = *(const ulonglong2*)&S.Wd1[i * 64 + ob];
            ulonglong2 w23 = *(const ulonglong2*)&S.Wd1[i * 64 + ob + 2];
            u64 y0 = S.ypc[(bp0 + 0) * 66 + i];
            u64 y1 = S.ypc[(bp0 + 1) * 66 + i];
            acc[0][0] = ffma2(y0, w01.x, acc[0][0]);
            acc[0][1] = ffma2(y0, w01.y, acc[0][1]);
            acc[0][2] = ffma2(y0, w23.x, acc[0][2]);
            acc[0][3] = ffma2(y0, w23.y, acc[0][3]);
            acc[1][0] = ffma2(y1, w01.x, acc[1][0]);
            acc[1][1] = ffma2(y1, w01.y, acc[1][1]);
            acc[1][2] = ffma2(y1, w23.x, acc[1][2]);
            acc[1][3] = ffma2(y1, w23.y, acc[1][3]);
        }
#pragma unroll
        for (int p = 0; p < 2; p++)
#pragma unroll
            for (int q = 0; q < 4; q++) {
                float2 v = unpack2(acc[p][q]);
                S.snr[(bp0 + p) * 66 + ob + q] = pack2(tanhf(v.x), tanhf(v.y));
            }
    }

    // ---------------- Phase A: net_out (j>0: tanh(y_prev @ Wf^T + bf)) ----------------
    if (j > 0) {
        u64 acc[2][4];
#pragma unroll
        for (int q = 0; q < 4; q++) {
            u64 bv = pack2(S.bfs[ob + q], S.bfs[ob + q]);
            acc[0][q] = bv; acc[1][q] = bv;
        }
#pragma unroll 8
        for (int i = 0; i < 64; i++) {
            ulonglong2 w01 = *(const ulonglong2*)&S.Wd0[i * 64 + ob];
            ulonglong2 w23 = *(const ulonglong2*)&S.Wd0[i * 64 + ob + 2];
            u64 y0 = S.ypp[(bp0 + 0) * 66 + i];
            u64 y1 = S.ypp[(bp0 + 1) * 66 + i];
            acc[0][0] = ffma2(y0, w01.x, acc[0][0]);
            acc[0][1] = ffma2(y0, w01.y, acc[0][1]);
            acc[0][2] = ffma2(y0, w23.x, acc[0][2]);
            acc[0][3] = ffma2(y0, w23.y, acc[0][3]);
            acc[1][0] = ffma2(y1, w01.x, acc[1][0]);
            acc[1][1] = ffma2(y1, w01.y, acc[1][1]);
            acc[1][2] = ffma2(y1, w23.x, acc[1][2]);
            acc[1][3] = ffma2(y1, w23.y, acc[1][3]);
        }
#pragma unroll
        for (int p = 0; p < 2; p++)
#pragma unroll
            for (int q = 0; q < 4; q++) {
                float2 v = unpack2(acc[p][q]);
                S.sno[(bp0 + p) * 66 + ob + q] = pack2(tanhf(v.x), tanhf(v.y));
            }
    }
    __syncthreads();

    // ---------------- Phase B loads: E_l -> Wd0, E_l_r -> Wd1 ----------------
    load_wdup(S.Wd0, El  + j * 4096, t);
    load_wdup(S.Wd1, Elr + j * 4096, t);
    __syncthreads();

    // ---------------- Phase B: drive = net_out @ El^T + net_rec @ Elr^T ----------------
    u64 accD[2][4];
#pragma unroll
    for (int p = 0; p < 2; p++)
#pragma unroll
        for (int q = 0; q < 4; q++) accD[p][q] = pack2(0.f, 0.f);

#pragma unroll 4
    for (int i = 0; i < 64; i++) {
        ulonglong2 e01 = *(const ulonglong2*)&S.Wd0[i * 64 + ob];
        ulonglong2 e23 = *(const ulonglong2*)&S.Wd0[i * 64 + ob + 2];
        ulonglong2 r01 = *(const ulonglong2*)&S.Wd1[i * 64 + ob];
        ulonglong2 r23 = *(const ulonglong2*)&S.Wd1[i * 64 + ob + 2];
        u64 n0 = S.sno[(bp0 + 0) * 66 + i];
        u64 n1 = S.sno[(bp0 + 1) * 66 + i];
        u64 m0 = S.snr[(bp0 + 0) * 66 + i];
        u64 m1 = S.snr[(bp0 + 1) * 66 + i];
        accD[0][0] = ffma2(n0, e01.x, accD[0][0]);
        accD[0][1] = ffma2(n0, e01.y, accD[0][1]);
        accD[0][2] = ffma2(n0, e23.x, accD[0][2]);
        accD[0][3] = ffma2(n0, e23.y, accD[0][3]);
        accD[1][0] = ffma2(n1, e01.x, accD[1][0]);
        accD[1][1] = ffma2(n1, e01.y, accD[1][1]);
        accD[1][2] = ffma2(n1, e23.x, accD[1][2]);
        accD[1][3] = ffma2(n1, e23.y, accD[1][3]);
        accD[0][0] = ffma2(m0, r01.x, accD[0][0]);
        accD[0][1] = ffma2(m0, r01.y, accD[0][1]);
        accD[0][2] = ffma2(m0, r23.x, accD[0][2]);
        accD[0][3] = ffma2(m0, r23.y, accD[0][3]);
        accD[1][0] = ffma2(m1, r01.x, accD[1][0]);
        accD[1][1] = ffma2(m1, r01.y, accD[1][1]);
        accD[1][2] = ffma2(m1, r23.x, accD[1][2]);
        accD[1][3] = ffma2(m1, r23.y, accD[1][3]);
    }

    // ---------------- Epilogue ----------------
    float vals[4][4];   // [local batch 0..3][o sub 0..3]
#pragma unroll
    for (int p = 0; p < 2; p++)
#pragma unroll
        for (int q = 0; q < 4; q++) {
            float2 dr  = unpack2(accD[p][q]);
            float2 nov = unpack2(S.sno[(bp0 + p) * 66 + ob + q]);
            float2 nrv = unpack2(S.snr[(bp0 + p) * 66 + ob + q]);
            float2 yv  = unpack2(S.ypc[(bp0 + p) * 66 + ob + q]);
            float  it  = S.itau[ob + q];
            vals[2 * p + 0][q] = (yv.x + DT_C * dr.x) /
                                 (1.f + DT_C * (it + fabsf(nov.x) + fabsf(nrv.x)));
            vals[2 * p + 1][q] = (yv.y + DT_C * dr.y) /
                                 (1.f + DT_C * (it + fabsf(nov.y) + fabsf(nrv.y)));
        }
#pragma unroll
    for (int bl = 0; bl < 4; bl++) {
        int row = row0 + ty * 4 + bl;
        float4 v = make_float4(vals[bl][0], vals[bl][1], vals[bl][2], vals[bl][3]);
        *(float4*)&out[row * NTOT + j * 64 + ob] = v;
    }
}

// ---------------------------------------------------------------------------
extern "C" void kernel_launch(void* const* d_in, const int* in_sizes, int n_in,
                              void* d_out, int out_size) {
    const float* y   = (const float*)d_in[0];
    const float* u_t = (const float*)d_in[1];
    const float* tau = (const float*)d_in[2];
    const float* Wi  = (const float*)d_in[3];
    const float* bi  = (const float*)d_in[4];
    const float* Wf  = (const float*)d_in[5];
    const float* bf  = (const float*)d_in[6];
    const float* Wr  = (const float*)d_in[7];
    const float* br  = (const float*)d_in[8];
    const float* El  = (const float*)d_in[9];
    const float* Elr = (const float*)d_in[10];
    float* out = (float*)d_out;

    cudaFuncSetAttribute(ltc_main, cudaFuncAttributeMaxDynamicSharedMemorySize,
                         (int)sizeof(SmemMain));

    net0_kernel<<<BATCH / 64, 256>>>(u_t, Wi, bi);
    ltc_main<<<dim3(BATCH / 64, NB), 256, sizeof(SmemMain)>>>(
        y, tau, Wf, bf, Wr, br, El, Elr, out);
}

// round 4
// speedup vs baseline: 8.7230x; 8.7221x over previous
#include <cuda_runtime.h>
#include <cuda_bf16.h>
#include <cstdint>

#define BATCH   4096
#define NB      64
#define IN_DIM  256
#define NTOT    4096
#define DT_C    0.05f
#define TAU_EPS 1e-6f

// bf16 tile row pitch: 72 elems = 144 bytes (odd 16B-groups -> conflict-free ldmatrix)
#define PITCH   144

// ---------------- SMEM layout (byte offsets) ----------------
#define A0_OFF  0                       // 128 x 64 bf16 (y_prev/net0 -> net_out)
#define A1_OFF  18432                   // 128 x 64 bf16 (y_cur -> net_rec)
#define W0_OFF  36864                   // W_fwd[j-1] 64x64 bf16
#define W1_OFF  46080                   // W_rec[j]
#define W2_OFF  55296                   // E_l[j]
#define W3_OFF  64512                   // E_l_r[j]
#define YB_OFF  73728                   // 128 x 66 fp32 exact y -> y_new
#define BR_OFF  (YB_OFF + 128*66*4)     // 107520
#define BF_OFF  (BR_OFF + 256)
#define IT_OFF  (BF_OFF + 256)
#define SMEM_TOTAL (IT_OFF + 256)       // 108288 bytes -> 2 CTAs/SM

__device__ float g_net0[BATCH * 64];

// ---------------------------------------------------------------------------
// helpers
// ---------------------------------------------------------------------------
__device__ __forceinline__ uint32_t smem_u32(const void* p) {
    uint32_t a;
    asm("{ .reg .u64 t; cvta.to.shared.u64 t, %1; cvt.u32.u64 %0, t; }"
        : "=r"(a) : "l"(p));
    return a;
}
__device__ __forceinline__ float tanh_fast(float x) {
    float r; asm("tanh.approx.f32 %0, %1;" : "=f"(r) : "f"(x)); return r;
}
__device__ __forceinline__ uint32_t bf2(float lo, float hi) {
    uint32_t r;
    asm("cvt.rn.bf16x2.f32 %0, %1, %2;" : "=r"(r) : "f"(hi), "f"(lo));
    return r;
}
__device__ __forceinline__ float2 ubf2(uint32_t v) {
    __nv_bfloat162 b = *reinterpret_cast<__nv_bfloat162*>(&v);
    return __bfloat1622float2(b);
}

#define LDM4(r, addr) \
    asm volatile("ldmatrix.sync.aligned.m8n8.x4.shared.b16 {%0,%1,%2,%3}, [%4];" \
        : "=r"((r)[0]), "=r"((r)[1]), "=r"((r)[2]), "=r"((r)[3]) : "r"(addr))

__device__ __forceinline__ void mma16816(float* c, const uint32_t* a,
                                         uint32_t b0, uint32_t b1) {
    asm volatile(
        "mma.sync.aligned.m16n8k16.row.col.f32.bf16.bf16.f32 "
        "{%0,%1,%2,%3}, {%4,%5,%6,%7}, {%8,%9}, {%0,%1,%2,%3};"
        : "+f"(c[0]), "+f"(c[1]), "+f"(c[2]), "+f"(c[3])
        : "r"(a[0]), "r"(a[1]), "r"(a[2]), "r"(a[3]), "r"(b0), "r"(b1));
}

// Warp computes C[32 x 64] += A[32 x 64] * W[64 x 64]^T  (bf16 in, fp32 acc)
// acc[mt*8 + nt][4] per standard m16n8 fragment layout.
__device__ __forceinline__ void gemm32x64(uint32_t abase, uint32_t wbase,
                                          float acc[16][4], int lane, int warpM)
{
    uint32_t pa = abase + (uint32_t)((warpM + (lane & 7) + ((lane >> 3) & 1) * 8) * PITCH
                                     + ((lane >> 4) * 8) * 2);
    uint32_t pb = wbase + (uint32_t)((((lane & 7) + ((lane >> 4) & 1) * 8)) * PITCH
                                     + (((lane >> 3) & 1) * 8) * 2);
#pragma unroll
    for (int ks = 0; ks < 4; ks++) {
        uint32_t a0[4], a1[4];
        LDM4(a0, pa + ks * 32);
        LDM4(a1, pa + 16 * PITCH + ks * 32);
#pragma unroll
        for (int np = 0; np < 4; np++) {
            uint32_t b[4];
            LDM4(b, pb + np * 16 * PITCH + ks * 32);
            mma16816(acc[np * 2 + 0],     a0, b[0], b[1]);
            mma16816(acc[np * 2 + 1],     a0, b[2], b[3]);
            mma16816(acc[8 + np * 2 + 0], a1, b[0], b[1]);
            mma16816(acc[8 + np * 2 + 1], a1, b[2], b[3]);
        }
    }
}

__device__ __forceinline__ void tanh_store(const float acc[16][4], const float* bias,
                                           char* dst, int lane, int warpM)
{
    const int gm = warpM + (lane >> 2);
    const int nb = (lane & 3) * 2;
#pragma unroll
    for (int mt = 0; mt < 2; mt++)
#pragma unroll
        for (int nt = 0; nt < 8; nt++) {
            const float* c = acc[mt * 8 + nt];
            int n  = nt * 8 + nb;
            float b0 = bias[n], b1 = bias[n + 1];
            int m0 = gm + mt * 16;
            *(uint32_t*)(dst + m0 * PITCH + n * 2) =
                bf2(tanh_fast(c[0] + b0), tanh_fast(c[1] + b1));
            *(uint32_t*)(dst + (m0 + 8) * PITCH + n * 2) =
                bf2(tanh_fast(c[2] + b0), tanh_fast(c[3] + b1));
        }
}

// ---------------------------------------------------------------------------
// Kernel 1: net0 = tanh(u_t @ W_in^T + b_in)   (fp32 exact)
// ---------------------------------------------------------------------------
__global__ void __launch_bounds__(256) net0_kernel(const float* __restrict__ u,
                                                   const float* __restrict__ Wi,
                                                   const float* __restrict__ bi) {
    __shared__ float su[64][65];
    __shared__ float sw[64][65];
    const int t  = threadIdx.x;
    const int bt = blockIdx.x;
    const int tx = t & 15, ty = t >> 4;
    const int ob = tx * 4, bb = ty * 4;

    float acc[4][4];
#pragma unroll
    for (int p = 0; p < 4; p++)
#pragma unroll
        for (int q = 0; q < 4; q++) acc[p][q] = 0.f;

    for (int kc = 0; kc < IN_DIM; kc += 64) {
        __syncthreads();
#pragma unroll
        for (int r = 0; r < 4; r++) {
            int idx = t + r * 256;
            int row = idx >> 4;
            int col = (idx & 15) * 4;
            float4 v = *(const float4*)&u[(bt * 64 + row) * IN_DIM + kc + col];
            su[row][col + 0] = v.x; su[row][col + 1] = v.y;
            su[row][col + 2] = v.z; su[row][col + 3] = v.w;
            float4 w = *(const float4*)&Wi[row * IN_DIM + kc + col];
            sw[row][col + 0] = w.x; sw[row][col + 1] = w.y;
            sw[row][col + 2] = w.z; sw[row][col + 3] = w.w;
        }
        __syncthreads();
#pragma unroll 8
        for (int i = 0; i < 64; i++) {
            float wv[4], yv[4];
#pragma unroll
            for (int q = 0; q < 4; q++) wv[q] = sw[ob + q][i];
#pragma unroll
            for (int p = 0; p < 4; p++) yv[p] = su[bb + p][i];
#pragma unroll
            for (int p = 0; p < 4; p++)
#pragma unroll
                for (int q = 0; q < 4; q++) acc[p][q] = fmaf(yv[p], wv[q], acc[p][q]);
        }
    }
#pragma unroll
    for (int p = 0; p < 4; p++)
#pragma unroll
        for (int q = 0; q < 4; q++)
            g_net0[(bt * 64 + bb + p) * 64 + ob + q] = tanhf(acc[p][q] + bi[ob + q]);
}

// ---------------------------------------------------------------------------
// Kernel 2: main LTC update via mma.sync bf16. grid (32, 64), 128 threads.
// ---------------------------------------------------------------------------
__global__ void __launch_bounds__(128) ltc_main(
    const float* __restrict__ y,
    const float* __restrict__ tau_raw,
    const float* __restrict__ Wf,  const float* __restrict__ bfw,
    const float* __restrict__ Wr,  const float* __restrict__ brw,
    const float* __restrict__ El,  const float* __restrict__ Elr,
    float* __restrict__ out)
{
    extern __shared__ char sm[];
    const int t     = threadIdx.x;
    const int lane  = t & 31;
    const int warpM = (t >> 5) * 32;
    const int bt    = blockIdx.x;
    const int j     = blockIdx.y;
    const int row0  = bt * 128;

    float* yb   = (float*)(sm + YB_OFF);
    float* s_br = (float*)(sm + BR_OFF);
    float* s_bf = (float*)(sm + BF_OFF);
    float* s_it = (float*)(sm + IT_OFF);
    const uint32_t smb = smem_u32(sm);

    // ---------------- Stage ----------------
#pragma unroll
    for (int i = 0; i < 16; i++) {
        int idx = t + i * 128;
        int r = idx >> 4, c4 = idx & 15;
        float4 v = *(const float4*)&y[(row0 + r) * NTOT + j * 64 + c4 * 4];
        float* yrow = yb + r * 66 + c4 * 4;
        yrow[0] = v.x; yrow[1] = v.y; yrow[2] = v.z; yrow[3] = v.w;
        *(uint2*)(sm + A1_OFF + r * PITCH + c4 * 8) =
            make_uint2(bf2(v.x, v.y), bf2(v.z, v.w));
    }
    if (j > 0) {
#pragma unroll
        for (int i = 0; i < 16; i++) {
            int idx = t + i * 128;
            int r = idx >> 4, c4 = idx & 15;
            float4 v = *(const float4*)&y[(row0 + r) * NTOT + (j - 1) * 64 + c4 * 4];
            *(uint2*)(sm + A0_OFF + r * PITCH + c4 * 8) =
                make_uint2(bf2(v.x, v.y), bf2(v.z, v.w));
        }
    } else {
#pragma unroll
        for (int i = 0; i < 16; i++) {
            int idx = t + i * 128;
            int r = idx >> 4, c4 = idx & 15;
            float4 v = *(const float4*)&g_net0[(row0 + r) * 64 + c4 * 4];
            *(uint2*)(sm + A0_OFF + r * PITCH + c4 * 8) =
                make_uint2(bf2(v.x, v.y), bf2(v.z, v.w));
        }
    }
    {
        const float* wsrc[3] = { Wr + j * 4096, El + j * 4096, Elr + j * 4096 };
        const int    woff[3] = { W1_OFF, W2_OFF, W3_OFF };
#pragma unroll
        for (int wsel = 0; wsel < 3; wsel++) {
#pragma unroll
            for (int i = 0; i < 8; i++) {
                int idx = t + i * 128;
                int o = idx >> 4, c4 = idx & 15;
                float4 v = *(const float4*)&wsrc[wsel][o * 64 + c4 * 4];
                *(uint2*)(sm + woff[wsel] + o * PITCH + c4 * 8) =
                    make_uint2(bf2(v.x, v.y), bf2(v.z, v.w));
            }
        }
        if (j > 0) {
            const float* ws = Wf + (j - 1) * 4096;
#pragma unroll
            for (int i = 0; i < 8; i++) {
                int idx = t + i * 128;
                int o = idx >> 4, c4 = idx & 15;
                float4 v = *(const float4*)&ws[o * 64 + c4 * 4];
                *(uint2*)(sm + W0_OFF + o * PITCH + c4 * 8) =
                    make_uint2(bf2(v.x, v.y), bf2(v.z, v.w));
            }
        }
    }
    if (t < 64) {
        s_br[t] = brw[j * 64 + t];
        if (j > 0) s_bf[t] = bfw[(j - 1) * 64 + t];
        float x  = tau_raw[j * 64 + t];
        float sp = (x > 20.f) ? x : log1pf(expf(x));
        s_it[t]  = 1.0f / (sp + TAU_EPS);
    }
    __syncthreads();

    // ---------------- Phase 1: net_rec / net_fwd ----------------
    float acc[16][4];
#pragma unroll
    for (int i = 0; i < 16; i++)
#pragma unroll
        for (int q = 0; q < 4; q++) acc[i][q] = 0.f;
    gemm32x64(smb + A1_OFF, smb + W1_OFF, acc, lane, warpM);
    tanh_store(acc, s_br, sm + A1_OFF, lane, warpM);

    if (j > 0) {
#pragma unroll
        for (int i = 0; i < 16; i++)
#pragma unroll
            for (int q = 0; q < 4; q++) acc[i][q] = 0.f;
        gemm32x64(smb + A0_OFF, smb + W0_OFF, acc, lane, warpM);
        tanh_store(acc, s_bf, sm + A0_OFF, lane, warpM);
    }
    __syncwarp();   // each warp only touches its own 32 rows of A0/A1

    // ---------------- Phase 2: drive = net_out@El^T + net_rec@Elr^T ----------------
#pragma unroll
    for (int i = 0; i < 16; i++)
#pragma unroll
        for (int q = 0; q < 4; q++) acc[i][q] = 0.f;
    gemm32x64(smb + A0_OFF, smb + W2_OFF, acc, lane, warpM);
    gemm32x64(smb + A1_OFF, smb + W3_OFF, acc, lane, warpM);

    // ---------------- Epilogue ----------------
    {
        const int gm = warpM + (lane >> 2);
        const int nb = (lane & 3) * 2;
#pragma unroll
        for (int mt = 0; mt < 2; mt++)
#pragma unroll
            for (int nt = 0; nt < 8; nt++) {
                int n = nt * 8 + nb;
                float it0 = s_it[n], it1 = s_it[n + 1];
                const float* c = acc[mt * 8 + nt];
#pragma unroll
                for (int h = 0; h < 2; h++) {
                    int m = gm + mt * 16 + h * 8;
                    float2 no = ubf2(*(const uint32_t*)(sm + A0_OFF + m * PITCH + n * 2));
                    float2 nr = ubf2(*(const uint32_t*)(sm + A1_OFF + m * PITCH + n * 2));
                    float d0 = c[h * 2 + 0], d1 = c[h * 2 + 1];
                    float yv0 = yb[m * 66 + n], yv1 = yb[m * 66 + n + 1];
                    yb[m * 66 + n] =
                        (yv0 + DT_C * d0) / (1.f + DT_C * (it0 + fabsf(no.x) + fabsf(nr.x)));
                    yb[m * 66 + n + 1] =
                        (yv1 + DT_C * d1) / (1.f + DT_C * (it1 + fabsf(no.y) + fabsf(nr.y)));
                }
            }
    }
    __syncthreads();

    // ---------------- Coalesced store ----------------
#pragma unroll
    for (int i = 0; i < 16; i++) {
        int idx = t + i * 128;
        int r = idx >> 4, c4 = idx & 15;
        const float* yrow = yb + r * 66 + c4 * 4;
        float4 v = make_float4(yrow[0], yrow[1], yrow[2], yrow[3]);
        *(float4*)&out[(row0 + r) * NTOT + j * 64 + c4 * 4] = v;
    }
}

// ---------------------------------------------------------------------------
extern "C" void kernel_launch(void* const* d_in, const int* in_sizes, int n_in,
                              void* d_out, int out_size) {
    const float* y   = (const float*)d_in[0];
    const float* u_t = (const float*)d_in[1];
    const float* tau = (const float*)d_in[2];
    const float* Wi  = (const float*)d_in[3];
    const float* bi  = (const float*)d_in[4];
    const float* Wf  = (const float*)d_in[5];
    const float* bfw = (const float*)d_in[6];
    const float* Wr  = (const float*)d_in[7];
    const float* brw = (const float*)d_in[8];
    const float* El  = (const float*)d_in[9];
    const float* Elr = (const float*)d_in[10];
    float* out = (float*)d_out;

    cudaFuncSetAttribute(ltc_main, cudaFuncAttributeMaxDynamicSharedMemorySize,
                         SMEM_TOTAL);

    net0_kernel<<<BATCH / 64, 256>>>(u_t, Wi, bi);
    ltc_main<<<dim3(BATCH / 128, NB), 128, SMEM_TOTAL>>>(
        y, tau, Wf, bfw, Wr, brw, El, Elr, out);
}